// round 15
// baseline (speedup 1.0000x reference)
#include <cuda_runtime.h>
#include <cuda_fp16.h>
#include <cstdint>

// Problem constants
#define F_IN   64
#define F_OUT  64
#define IRREP  1771
#define NGRID  512
#define BATCH  256
#define RSTRIDE (F_OUT * IRREP)   // 113344

// fp16 planes.
// A_l: rows r=(b*d+m) [256d], cols k=(i*d+u) [64d]; base elem = 16384*c_off[l]
// B_l: rows n=(o*d+v) [64d],  cols k=(i*d+u) [64d]; base elem =  4096*c_off[l]
//      (scale/alpha folded into B).  B padded +64 rows*1344 for ragged N-tiles.
#define AELEMS 29016064            // 16384*1771
#define BELEMS_PAD 7340032         // 4096*1771 + 86016 pad
__device__ __half g_Ah[AELEMS];
__device__ __half g_Bh[BELEMS_PAD];
// psi GEMM operands: W fp16 (4096 x 512, K-contig), D^T fp16 (1792 x 512, padded)
__device__ __half g_Wh[4096 * 512];
__device__ __half g_Dh[1792 * 512];

// so3 blocks per l = 2d * ceil(d/2) = d(d+1); cumulative (tile 128x128)
__constant__ int c_cum3[12] = {0, 2, 14, 44, 100, 190, 322, 504, 744, 1050, 1430, 1892};
// cumsum of d^2 (12 entries so [l+1] is always valid)
__constant__ int c_off12[12] = {0, 1, 10, 35, 84, 165, 286, 455, 680, 969, 1330, 1771};

// ---------------------------------------------------------------------------
// helpers
// ---------------------------------------------------------------------------
__device__ __forceinline__ uint32_t smem_u32(const void* p) {
    uint32_t a;
    asm("{ .reg .u64 t; cvta.to.shared.u64 t, %1; cvt.u32.u64 %0, t; }" : "=r"(a) : "l"(p));
    return a;
}

__device__ __forceinline__ void cp16(uint32_t dst, const void* src) {
    asm volatile("cp.async.cg.shared.global [%0], [%1], 16;"
                 :: "r"(dst), "l"((uint64_t)__cvta_generic_to_global(src)) : "memory");
}
#define CP_COMMIT() asm volatile("cp.async.commit_group;" ::: "memory")
#define CP_WAIT1()  asm volatile("cp.async.wait_group 1;" ::: "memory")

#define LDSM_X4(r0, r1, r2, r3, addr) \
    asm volatile("ldmatrix.sync.aligned.m8n8.x4.shared.b16 {%0,%1,%2,%3}, [%4];" \
                 : "=r"(r0), "=r"(r1), "=r"(r2), "=r"(r3) : "r"(addr))

__device__ __forceinline__ void mma_f16(float* c, const uint32_t* a, uint32_t b0, uint32_t b1) {
    asm volatile(
        "mma.sync.aligned.m16n8k16.row.col.f32.f16.f16.f32 "
        "{%0,%1,%2,%3}, {%4,%5,%6,%7}, {%8,%9}, {%0,%1,%2,%3};"
        : "+f"(c[0]), "+f"(c[1]), "+f"(c[2]), "+f"(c[3])
        : "r"(a[0]), "r"(a[1]), "r"(a[2]), "r"(a[3]), "r"(b0), "r"(b1));
}

__device__ __forceinline__ uint32_t packh2(float a, float b) {
    __half2 h = __floats2half2_rn(a, b);
    return *(uint32_t*)&h;
}

// GEMM smem: K-chunk 64 -> A stage 16KB (128 rows x 128B) + B stage 16KB
#define STAGE_BYTES 32768
#define OFF_SA 0
#define OFF_SB 16384
#define GEMM_SMEM (3 * STAGE_BYTES)   // 96 KB, 3 stages

// ---------------------------------------------------------------------------
// Kernel W0: w f32 -> g_Wh fp16 (same layout).
// ---------------------------------------------------------------------------
__global__ __launch_bounds__(256) void wprep_kernel(const float* __restrict__ W) {
    const int idx = (blockIdx.x * 256 + threadIdx.x) * 8;
    float4 v0 = *(const float4*)(W + idx);
    float4 v1 = *(const float4*)(W + idx + 4);
    uint4 out;
    out.x = packh2(v0.x, v0.y);
    out.y = packh2(v0.z, v0.w);
    out.z = packh2(v1.x, v1.y);
    out.w = packh2(v1.z, v1.w);
    *(uint4*)(g_Wh + idx) = out;
}

// ---------------------------------------------------------------------------
// Kernel D0: D (512,1771) f32 -> g_Dh fp16 transposed (1792,512), zero pad.
// ---------------------------------------------------------------------------
__global__ __launch_bounds__(256) void dprep_kernel(const float* __restrict__ D) {
    __shared__ float sm[32][33];
    const int c0 = blockIdx.x * 32;
    const int n0 = blockIdx.y * 32;
    const int tx = threadIdx.x;
    const int ty = threadIdx.y;

#pragma unroll
    for (int j = 0; j < 4; j++) {
        const int n = ty + j * 8;
        const int c = c0 + tx;
        sm[n][tx] = (c < IRREP) ? D[(n0 + n) * IRREP + c] : 0.0f;
    }
    __syncthreads();

#pragma unroll
    for (int j = 0; j < 4; j++) {
        const int r = ty + j * 8;
        g_Dh[(size_t)(c0 + r) * 512 + n0 + tx] = __float2half_rn(sm[tx][r]);
    }
}

// ---------------------------------------------------------------------------
// Kernel 0: xprep — x f32 -> per-l fp16 A planes (m-group parallel phase 2).
// ---------------------------------------------------------------------------
__global__ __launch_bounds__(256) void xprep_kernel(const float* __restrict__ X) {
    __shared__ float sm[16 * 441];
    const int b  = blockIdx.x;
    const int l  = blockIdx.y;
    const int ic = blockIdx.z;
    const int d  = 2 * l + 1;
    const int d2 = d * d;
    const int off = c_off12[l];
    const int Kl = 64 * d;
    const int tid = threadIdx.x;

    const float* xb = X + (size_t)b * RSTRIDE + (ic * 16) * IRREP + off;
#pragma unroll 4
    for (int ii = 0; ii < 16; ii++)
        for (int j = tid; j < d2; j += 256)
            sm[ii * d2 + j] = xb[ii * IRREP + j];
    __syncthreads();

    const int ppc = 8 * d;
    const int nm  = 256 / ppc;
    if (tid < ppc * nm) {
        const int mg = tid / ppc;
        const int p  = tid - mg * ppc;
        const int k0 = 2 * p;
        const int k1 = k0 + 1;
        const int i0 = k0 / d, u0 = k0 - i0 * d;
        const int i1 = k1 / d, u1 = k1 - i1 * d;
        const int s0 = i0 * d2 + u0 * d;
        const int s1 = i1 * d2 + u1 * d;

        const int Abase = 16384 * off;
        const int colBase = ic * 16 * d + k0;
        int rowIdx = (b * d + mg) * Kl + colBase;
        for (int m = mg; m < d; m += nm, rowIdx += nm * Kl) {
            *(uint32_t*)(g_Ah + Abase + rowIdx) = packh2(sm[s0 + m], sm[s1 + m]);
        }
    }
}

// ---------------------------------------------------------------------------
// GEMM core geometry (shared by psi and so3):
//   CTA tile 128x128, K-chunk 64, smem rows 128B, swizzle chunk ^= (row&7).
//   cp.async: thread -> row = tid&127, 4 chunks (half = tid>>7), A and B.
//   8 warps: wm=wid>>1 (32-row tile), wn=wid&1 (64-col tile).
//   Per iter: 4 k16 groups -> 24 LDSM + 64 HMMA per warp between barriers.
// ---------------------------------------------------------------------------

// ---------------------------------------------------------------------------
// Kernel 1: psi GEMM.  M=4096 (32), N=1792 (14), K=512 (8 x 64).
// Epilogue scatters into g_Bh (scale*alpha folded).
// ---------------------------------------------------------------------------
__global__ __launch_bounds__(256, 2) void psi_mma_kernel(void) {
    extern __shared__ __align__(1024) char dsm[];
    const uint32_t sb = smem_u32(dsm);

    const int tid  = threadIdx.x;
    const int wid  = tid >> 5;
    const int lane = tid & 31;
    const int wm = wid >> 1;
    const int wn = wid & 1;

    const int tileN = blockIdx.x;   // 0..13
    const int tileM = blockIdx.y;   // 0..31
    const int nIter = 8;            // K=512 / 64

    // cp.async geometry
    const int grow = tid & 127;
    const int gc0  = (tid >> 7) * 4;           // chunks gc0..gc0+3
    const int gsw  = grow & 7;
    uint32_t gdst[4];
#pragma unroll
    for (int c = 0; c < 4; c++)
        gdst[c] = (uint32_t)(grow * 128 + (((gc0 + c) ^ gsw) << 4));
    const __half* asrc = g_Wh + (size_t)(tileM * 128 + grow) * 512 + gc0 * 8;
    const __half* bsrc = g_Dh + (size_t)(tileN * 128 + grow) * 512 + gc0 * 8;

    // ldmatrix geometry
    const int a_row = wm * 32 + (lane & 15);
    const int a_cbit = lane >> 4;
    const int b_row = wn * 64 + (lane & 7) + ((lane >> 4) << 3);
    const int b_cbit = (lane >> 3) & 1;
    uint32_t aRB[2], bRB[4];
    int aSW[2], bSW[4];
#pragma unroll
    for (int mt = 0; mt < 2; mt++) {
        const int row = a_row + mt * 16;
        aRB[mt] = (uint32_t)(row * 128);
        aSW[mt] = row & 7;
    }
#pragma unroll
    for (int ng = 0; ng < 4; ng++) {
        const int row = b_row + ng * 16;
        bRB[ng] = (uint32_t)(row * 128);
        bSW[ng] = row & 7;
    }

    // prologue: stages 0,1
#pragma unroll
    for (int s = 0; s < 2; s++) {
        const uint32_t dst = sb + (uint32_t)s * STAGE_BYTES;
        const int kt = s * 64;
#pragma unroll
        for (int c = 0; c < 4; c++) {
            cp16(dst + OFF_SA + gdst[c], asrc + kt + c * 8);
            cp16(dst + OFF_SB + gdst[c], bsrc + kt + c * 8);
        }
        CP_COMMIT();
    }

    float acc[2][8][4] = {};
    int bufc = 0;   // it % 3

    for (int it = 0; it < nIter; ++it) {
        CP_WAIT1();
        __syncthreads();
        {
            const int s = it + 2;
            if (s < nIter) {
                int bufn = bufc + 2; if (bufn >= 3) bufn -= 3;
                const uint32_t dst = sb + (uint32_t)bufn * STAGE_BYTES;
                const int kt = s * 64;
#pragma unroll
                for (int c = 0; c < 4; c++) {
                    cp16(dst + OFF_SA + gdst[c], asrc + kt + c * 8);
                    cp16(dst + OFF_SB + gdst[c], bsrc + kt + c * 8);
                }
            }
            CP_COMMIT();
        }

        const uint32_t sbase = sb + (uint32_t)bufc * STAGE_BYTES;
#pragma unroll
        for (int ks = 0; ks < 4; ks++) {
            uint32_t a[2][4], b[4][4];
#pragma unroll
            for (int mt = 0; mt < 2; mt++)
                LDSM_X4(a[mt][0], a[mt][1], a[mt][2], a[mt][3],
                        sbase + OFF_SA + aRB[mt] + (((ks * 2 + a_cbit) ^ aSW[mt]) << 4));
#pragma unroll
            for (int ng = 0; ng < 4; ng++)
                LDSM_X4(b[ng][0], b[ng][1], b[ng][2], b[ng][3],
                        sbase + OFF_SB + bRB[ng] + (((ks * 2 + b_cbit) ^ bSW[ng]) << 4));
#pragma unroll
            for (int mt = 0; mt < 2; mt++)
#pragma unroll
                for (int nt = 0; nt < 8; nt++) {
                    const int ng = nt >> 1, pr = (nt & 1) * 2;
                    mma_f16(acc[mt][nt], a[mt], b[ng][pr], b[ng][pr + 1]);
                }
        }
        if (++bufc == 3) bufc = 0;
    }

    // Epilogue: scatter into B planes. c -> (l, u, v); r -> (i, o).
    const float scale = 0.04419417382415922f;  // 1/sqrt(512)
#pragma unroll
    for (int nt = 0; nt < 8; nt++) {
#pragma unroll
        for (int e = 0; e < 2; e++) {
            const int c = tileN * 128 + wn * 64 + nt * 8 + (lane & 3) * 2 + e;
            if (c >= IRREP) continue;
            int l = 0;
            while (c >= c_off12[l + 1]) ++l;
            const int d   = 2 * l + 1;
            const int off = c_off12[l];
            const int rel = c - off;
            const int u = rel / d;
            const int v = rel - u * d;
            const int Kl = 64 * d;
            const int Bbase = 4096 * off;
            const float sa = scale * rsqrtf(64.0f * (float)d);
#pragma unroll
            for (int mt = 0; mt < 2; mt++)
#pragma unroll
                for (int h = 0; h < 2; h++) {
                    const int r = tileM * 128 + wm * 32 + mt * 16 + (lane >> 2) + h * 8;
                    const int i = r >> 6;
                    const int o = r & 63;
                    g_Bh[Bbase + (o * d + v) * Kl + i * d + u] =
                        __float2half_rn(acc[mt][nt][h * 2 + e] * sa);
                }
        }
    }
}

// ---------------------------------------------------------------------------
// Kernel 2: so3 GEMM per l, 128x128 tile, K-chunk 64 (nIter = d).
// ---------------------------------------------------------------------------
__global__ __launch_bounds__(256, 2) void so3_kernel(float* __restrict__ O) {
    extern __shared__ __align__(1024) char dsm[];
    __shared__ int colOff[128];
    const uint32_t sb = smem_u32(dsm);

    const int tid  = threadIdx.x;
    const int wid  = tid >> 5;
    const int lane = tid & 31;
    const int wm = wid >> 1;
    const int wn = wid & 1;

    const int bid = (int)gridDim.x - 1 - (int)blockIdx.x;   // largest l first
    int l = 0;
    while (bid >= c_cum3[l + 1]) ++l;
    const int d     = 2 * l + 1;
    const int off   = c_off12[l];
    const int loc   = bid - c_cum3[l];
    const int nN    = (d + 1) >> 1;
    const int tileM = loc / nN;
    const int tileN = loc - tileM * nN;
    const int Kl    = 64 * d;
    const int nIter = d;
    const int Nvalid = 64 * d;

    const int Abase = 16384 * off;
    const int Bbase = 4096 * off;

    if (tid < 128) {
        const int gc = tileN * 128 + tid;
        if (gc < Nvalid) {
            const int o = gc / d;
            const int v = gc - o * d;
            colOff[tid] = o * IRREP + v * d;
        } else {
            colOff[tid] = 0;
        }
    }

    // cp.async geometry
    const int grow = tid & 127;
    const int gc0  = (tid >> 7) * 4;
    const int gsw  = grow & 7;
    uint32_t gdst[4];
#pragma unroll
    for (int c = 0; c < 4; c++)
        gdst[c] = (uint32_t)(grow * 128 + (((gc0 + c) ^ gsw) << 4));
    const int asrcRow = Abase + (tileM * 128 + grow) * Kl + gc0 * 8;
    const int bsrcRow = Bbase + (tileN * 128 + grow) * Kl + gc0 * 8;  // ragged rows hit pad

    // ldmatrix geometry
    const int a_row = wm * 32 + (lane & 15);
    const int a_cbit = lane >> 4;
    const int b_row = wn * 64 + (lane & 7) + ((lane >> 4) << 3);
    const int b_cbit = (lane >> 3) & 1;
    uint32_t aRB[2], bRB[4];
    int aSW[2], bSW[4];
#pragma unroll
    for (int mt = 0; mt < 2; mt++) {
        const int row = a_row + mt * 16;
        aRB[mt] = (uint32_t)(row * 128);
        aSW[mt] = row & 7;
    }
#pragma unroll
    for (int ng = 0; ng < 4; ng++) {
        const int row = b_row + ng * 16;
        bRB[ng] = (uint32_t)(row * 128);
        bSW[ng] = row & 7;
    }

    // prologue: stages 0,1 (guarded)
#pragma unroll
    for (int s = 0; s < 2; s++) {
        if (s < nIter) {
            const uint32_t dst = sb + (uint32_t)s * STAGE_BYTES;
            const int kt = s * 64;
#pragma unroll
            for (int c = 0; c < 4; c++) {
                cp16(dst + OFF_SA + gdst[c], g_Ah + asrcRow + kt + c * 8);
                cp16(dst + OFF_SB + gdst[c], g_Bh + bsrcRow + kt + c * 8);
            }
        }
        CP_COMMIT();
    }

    float acc[2][8][4] = {};
    int bufc = 0;

    for (int it = 0; it < nIter; ++it) {
        CP_WAIT1();
        __syncthreads();
        {
            const int s = it + 2;
            if (s < nIter) {
                int bufn = bufc + 2; if (bufn >= 3) bufn -= 3;
                const uint32_t dst = sb + (uint32_t)bufn * STAGE_BYTES;
                const int kt = s * 64;
#pragma unroll
                for (int c = 0; c < 4; c++) {
                    cp16(dst + OFF_SA + gdst[c], g_Ah + asrcRow + kt + c * 8);
                    cp16(dst + OFF_SB + gdst[c], g_Bh + bsrcRow + kt + c * 8);
                }
            }
            CP_COMMIT();
        }

        const uint32_t sbase = sb + (uint32_t)bufc * STAGE_BYTES;
#pragma unroll
        for (int ks = 0; ks < 4; ks++) {
            uint32_t a[2][4], b[4][4];
#pragma unroll
            for (int mt = 0; mt < 2; mt++)
                LDSM_X4(a[mt][0], a[mt][1], a[mt][2], a[mt][3],
                        sbase + OFF_SA + aRB[mt] + (((ks * 2 + a_cbit) ^ aSW[mt]) << 4));
#pragma unroll
            for (int ng = 0; ng < 4; ng++)
                LDSM_X4(b[ng][0], b[ng][1], b[ng][2], b[ng][3],
                        sbase + OFF_SB + bRB[ng] + (((ks * 2 + b_cbit) ^ bSW[ng]) << 4));
#pragma unroll
            for (int mt = 0; mt < 2; mt++)
#pragma unroll
                for (int nt = 0; nt < 8; nt++) {
                    const int ng = nt >> 1, pr = (nt & 1) * 2;
                    mma_f16(acc[mt][nt], a[mt], b[ng][pr], b[ng][pr + 1]);
                }
        }
        if (++bufc == 3) bufc = 0;
    }

    // Epilogue: scatter f32; skip invalid (ragged) columns.
#pragma unroll
    for (int mt = 0; mt < 2; mt++)
#pragma unroll
        for (int h = 0; h < 2; h++) {
            const int r = tileM * 128 + wm * 32 + mt * 16 + (lane >> 2) + h * 8;
            const int b = r / d;
            const int m = r - b * d;
            float* orow = O + b * RSTRIDE + off + m;
#pragma unroll
            for (int nt = 0; nt < 8; nt++) {
                const int c0 = wn * 64 + nt * 8 + (lane & 3) * 2;
                if (tileN * 128 + c0 < Nvalid) {
                    orow[colOff[c0]]     = acc[mt][nt][h * 2 + 0];
                    orow[colOff[c0 + 1]] = acc[mt][nt][h * 2 + 1];
                }
            }
        }
}

// ---------------------------------------------------------------------------
// Launch: inputs: x (256,64,1771) f32, D (512,1771) f32, w (64,64,512) f32.
// ---------------------------------------------------------------------------
extern "C" void kernel_launch(void* const* d_in, const int* in_sizes, int n_in,
                              void* d_out, int out_size) {
    const float* x = (const float*)d_in[0];
    const float* D = (const float*)d_in[1];
    const float* w = (const float*)d_in[2];
    float* out = (float*)d_out;

    cudaFuncSetAttribute(psi_mma_kernel, cudaFuncAttributeMaxDynamicSharedMemorySize, GEMM_SMEM);
    cudaFuncSetAttribute(so3_kernel,     cudaFuncAttributeMaxDynamicSharedMemorySize, GEMM_SMEM);

    wprep_kernel<<<1024, 256>>>(w);                       // w -> fp16
    dprep_kernel<<<dim3(56, 16), dim3(32, 8)>>>(D);       // D -> fp16 transposed+padded
    xprep_kernel<<<dim3(BATCH, 11, 4), 256>>>(x);         // x -> A plane (fp16)
    psi_mma_kernel<<<dim3(14, 32), 256, GEMM_SMEM>>>();   // W@D -> B plane (tensor cores)
    so3_kernel<<<1892, 256, GEMM_SMEM>>>(out);
}

// round 17
// speedup vs baseline: 1.0527x; 1.0527x over previous
#include <cuda_runtime.h>
#include <cuda_fp16.h>
#include <cstdint>

// Problem constants
#define F_IN   64
#define F_OUT  64
#define IRREP  1771
#define NGRID  512
#define BATCH  256
#define RSTRIDE (F_OUT * IRREP)   // 113344

// fp16 planes.
// A_l: rows r=(b*d+m) [256d], cols k=(i*d+u) [64d]; base elem = 16384*c_off[l]
// B_l: rows n=(o*d+v) [64d],  cols k=(i*d+u) [64d]; base elem =  4096*c_off[l]
//      (scale/alpha folded into B)
#define AELEMS 29016064   // 16384*1771
#define BELEMS 7254016    // 4096*1771
__device__ __half g_Ah[AELEMS];
__device__ __half g_Bh[BELEMS];
// psi GEMM operands: W fp16 (4096 x 512, K-contig), D^T fp16 (1792 x 512, padded)
__device__ __half g_Wh[4096 * 512];
__device__ __half g_Dh[1792 * 512];

// stage-2 blocks per l = 2*d*d (tile 128x64); cumulative
__constant__ int c_cum2[12] = {0, 2, 20, 70, 168, 330, 572, 910, 1360, 1938, 2660, 3542};
// cumsum of d^2 (12 entries so [l+1] is always valid)
__constant__ int c_off12[12] = {0, 1, 10, 35, 84, 165, 286, 455, 680, 969, 1330, 1771};

// ---------------------------------------------------------------------------
// helpers
// ---------------------------------------------------------------------------
__device__ __forceinline__ uint32_t smem_u32(const void* p) {
    uint32_t a;
    asm("{ .reg .u64 t; cvta.to.shared.u64 t, %1; cvt.u32.u64 %0, t; }" : "=r"(a) : "l"(p));
    return a;
}

__device__ __forceinline__ void cp16(uint32_t dst, const void* src) {
    asm volatile("cp.async.cg.shared.global [%0], [%1], 16;"
                 :: "r"(dst), "l"((uint64_t)__cvta_generic_to_global(src)) : "memory");
}
#define CP_COMMIT() asm volatile("cp.async.commit_group;" ::: "memory")
#define CP_WAIT2()  asm volatile("cp.async.wait_group 2;" ::: "memory")

#define LDSM_X4(r0, r1, r2, r3, addr) \
    asm volatile("ldmatrix.sync.aligned.m8n8.x4.shared.b16 {%0,%1,%2,%3}, [%4];" \
                 : "=r"(r0), "=r"(r1), "=r"(r2), "=r"(r3) : "r"(addr))

__device__ __forceinline__ void mma_f16(float* c, const uint32_t* a, uint32_t b0, uint32_t b1) {
    asm volatile(
        "mma.sync.aligned.m16n8k16.row.col.f32.f16.f16.f32 "
        "{%0,%1,%2,%3}, {%4,%5,%6,%7}, {%8,%9}, {%0,%1,%2,%3};"
        : "+f"(c[0]), "+f"(c[1]), "+f"(c[2]), "+f"(c[3])
        : "r"(a[0]), "r"(a[1]), "r"(a[2]), "r"(a[3]), "r"(b0), "r"(b1));
}

__device__ __forceinline__ uint32_t packh2(float a, float b) {
    __half2 h = __floats2half2_rn(a, b);
    return *(uint32_t*)&h;
}

// ---------------------------------------------------------------------------
// Kernel W0: w f32 -> g_Wh fp16 (same layout).
// ---------------------------------------------------------------------------
__global__ __launch_bounds__(256) void wprep_kernel(const float* __restrict__ W) {
    const int idx = (blockIdx.x * 256 + threadIdx.x) * 8;
    float4 v0 = *(const float4*)(W + idx);
    float4 v1 = *(const float4*)(W + idx + 4);
    uint4 out;
    out.x = packh2(v0.x, v0.y);
    out.y = packh2(v0.z, v0.w);
    out.z = packh2(v1.x, v1.y);
    out.w = packh2(v1.z, v1.w);
    *(uint4*)(g_Wh + idx) = out;
}

// ---------------------------------------------------------------------------
// Kernel D0: D (512,1771) f32 -> g_Dh fp16 transposed (1792,512), zero pad.
// ---------------------------------------------------------------------------
__global__ __launch_bounds__(256) void dprep_kernel(const float* __restrict__ D) {
    __shared__ float sm[32][33];
    const int c0 = blockIdx.x * 32;
    const int n0 = blockIdx.y * 32;
    const int tx = threadIdx.x;
    const int ty = threadIdx.y;

#pragma unroll
    for (int j = 0; j < 4; j++) {
        const int n = ty + j * 8;
        const int c = c0 + tx;
        sm[n][tx] = (c < IRREP) ? D[(n0 + n) * IRREP + c] : 0.0f;
    }
    __syncthreads();

#pragma unroll
    for (int j = 0; j < 4; j++) {
        const int r = ty + j * 8;
        g_Dh[(size_t)(c0 + r) * 512 + n0 + tx] = __float2half_rn(sm[tx][r]);
    }
}

// ---------------------------------------------------------------------------
// Kernel 0: xprep — x f32 -> per-l fp16 A planes (m-group parallel phase 2).
// ---------------------------------------------------------------------------
__global__ __launch_bounds__(256) void xprep_kernel(const float* __restrict__ X) {
    __shared__ float sm[16 * 441];
    const int b  = blockIdx.x;
    const int l  = blockIdx.y;
    const int ic = blockIdx.z;
    const int d  = 2 * l + 1;
    const int d2 = d * d;
    const int off = c_off12[l];
    const int Kl = 64 * d;
    const int tid = threadIdx.x;

    const float* xb = X + (size_t)b * RSTRIDE + (ic * 16) * IRREP + off;
#pragma unroll 4
    for (int ii = 0; ii < 16; ii++)
        for (int j = tid; j < d2; j += 256)
            sm[ii * d2 + j] = xb[ii * IRREP + j];
    __syncthreads();

    const int ppc = 8 * d;
    const int nm  = 256 / ppc;
    if (tid < ppc * nm) {
        const int mg = tid / ppc;
        const int p  = tid - mg * ppc;
        const int k0 = 2 * p;
        const int k1 = k0 + 1;
        const int i0 = k0 / d, u0 = k0 - i0 * d;
        const int i1 = k1 / d, u1 = k1 - i1 * d;
        const int s0 = i0 * d2 + u0 * d;
        const int s1 = i1 * d2 + u1 * d;

        const int Abase = 16384 * off;
        const int colBase = ic * 16 * d + k0;
        int rowIdx = (b * d + mg) * Kl + colBase;
        for (int m = mg; m < d; m += nm, rowIdx += nm * Kl) {
            *(uint32_t*)(g_Ah + Abase + rowIdx) = packh2(sm[s0 + m], sm[s1 + m]);
        }
    }
}

// ---------------------------------------------------------------------------
// Kernel 1: psi GEMM on tensor cores (R10 config: 128x64 tile, K-chunk 32).
// ---------------------------------------------------------------------------
#define STAGE_BYTES 12288
#define OFF_SA 0
#define OFF_SB 8192
#define SO3_SMEM (4 * STAGE_BYTES)

__global__ __launch_bounds__(256, 3) void psi_mma_kernel(void) {
    extern __shared__ __align__(1024) char dsm[];
    const uint32_t sb = smem_u32(dsm);

    const int tid  = threadIdx.x;
    const int wid  = tid >> 5;
    const int lane = tid & 31;
    const int wm = wid >> 1;
    const int wn = wid & 1;

    const int tileN = blockIdx.x;   // 0..27
    const int tileM = blockIdx.y;   // 0..31
    const int nIter = 16;           // K=512 / 32

    const int arow = tid & 127;
    const int acsel = (tid >> 7) * 2;
    const int asw = (arow >> 1) & 3;
    const uint32_t adst0 = (uint32_t)(arow * 64 + (((acsel + 0) ^ asw) << 4));
    const uint32_t adst1 = (uint32_t)(arow * 64 + (((acsel + 1) ^ asw) << 4));
    const __half* asrc = g_Wh + (size_t)(tileM * 128 + arow) * 512;

    const int brow = tid >> 2;
    const int bcsel = tid & 3;
    const uint32_t bdst = (uint32_t)(brow * 64 + ((bcsel ^ ((brow >> 1) & 3)) << 4));
    const __half* bsrc = g_Dh + (size_t)(tileN * 64 + brow) * 512;

    const int a_r0 = wm * 32 + (lane & 15);
    const int a_cbit = lane >> 4;
    const int b_r0 = wn * 32 + (lane & 7) + ((lane >> 4) << 3);
    const int b_cbit = (lane >> 3) & 1;

    uint32_t aoff[2][2], boff[2][2];
#pragma unroll
    for (int mt = 0; mt < 2; mt++) {
        const int row = a_r0 + mt * 16;
        const int sw = (row >> 1) & 3;
#pragma unroll
        for (int ks = 0; ks < 2; ks++)
            aoff[mt][ks] = (uint32_t)(row * 64 + (((ks * 2 + a_cbit) ^ sw) << 4));
    }
#pragma unroll
    for (int ng = 0; ng < 2; ng++) {
        const int row = b_r0 + ng * 16;
        const int sw = (row >> 1) & 3;
#pragma unroll
        for (int ks = 0; ks < 2; ks++)
            boff[ng][ks] = (uint32_t)(row * 64 + (((ks * 2 + b_cbit) ^ sw) << 4));
    }

#pragma unroll
    for (int s = 0; s < 3; s++) {
        const uint32_t dst = sb + (uint32_t)(s & 3) * STAGE_BYTES;
        const int kt = s * 32;
        cp16(dst + OFF_SA + adst0, asrc + kt + (acsel + 0) * 8);
        cp16(dst + OFF_SA + adst1, asrc + kt + (acsel + 1) * 8);
        cp16(dst + OFF_SB + bdst,  bsrc + kt + bcsel * 8);
        CP_COMMIT();
    }

    float acc[2][4][4] = {};

    for (int it = 0; it < nIter; ++it) {
        CP_WAIT2();
        __syncthreads();
        {
            const int s = it + 3;
            if (s < nIter) {
                const uint32_t dst = sb + (uint32_t)(s & 3) * STAGE_BYTES;
                const int kt = s * 32;
                cp16(dst + OFF_SA + adst0, asrc + kt + (acsel + 0) * 8);
                cp16(dst + OFF_SA + adst1, asrc + kt + (acsel + 1) * 8);
                cp16(dst + OFF_SB + bdst,  bsrc + kt + bcsel * 8);
            }
            CP_COMMIT();
        }

        const uint32_t sbase = sb + (uint32_t)(it & 3) * STAGE_BYTES;
#pragma unroll
        for (int ks = 0; ks < 2; ks++) {
            uint32_t a[2][4], b[2][4];
#pragma unroll
            for (int mt = 0; mt < 2; mt++)
                LDSM_X4(a[mt][0], a[mt][1], a[mt][2], a[mt][3],
                        sbase + OFF_SA + aoff[mt][ks]);
#pragma unroll
            for (int ng = 0; ng < 2; ng++)
                LDSM_X4(b[ng][0], b[ng][1], b[ng][2], b[ng][3],
                        sbase + OFF_SB + boff[ng][ks]);
#pragma unroll
            for (int mt = 0; mt < 2; mt++)
#pragma unroll
                for (int nt = 0; nt < 4; nt++) {
                    const int ng = nt >> 1, pr = (nt & 1) * 2;
                    mma_f16(acc[mt][nt], a[mt], b[ng][pr], b[ng][pr + 1]);
                }
        }
    }

    const float scale = 0.04419417382415922f;  // 1/sqrt(512)
#pragma unroll
    for (int nt = 0; nt < 4; nt++) {
#pragma unroll
        for (int e = 0; e < 2; e++) {
            const int c = tileN * 64 + wn * 32 + nt * 8 + (lane & 3) * 2 + e;
            if (c >= IRREP) continue;
            int l = 0;
            while (c >= c_off12[l + 1]) ++l;
            const int d   = 2 * l + 1;
            const int off = c_off12[l];
            const int rel = c - off;
            const int u = rel / d;
            const int v = rel - u * d;
            const int Kl = 64 * d;
            const int Bbase = 4096 * off;
            const float sa = scale * rsqrtf(64.0f * (float)d);
#pragma unroll
            for (int mt = 0; mt < 2; mt++)
#pragma unroll
                for (int h = 0; h < 2; h++) {
                    const int r = tileM * 128 + wm * 32 + mt * 16 + (lane >> 2) + h * 8;
                    const int i = r >> 6;
                    const int o = r & 63;
                    g_Bh[Bbase + (o * d + v) * Kl + i * d + u] =
                        __float2half_rn(acc[mt][nt][h * 2 + e] * sa);
                }
        }
    }
}

// ---------------------------------------------------------------------------
// Kernel 2: so3 GEMM per l (R10 config: 128x64 tile, K-chunk 32, 4 stages).
// ---------------------------------------------------------------------------
__global__ __launch_bounds__(256, 3) void so3_kernel(float* __restrict__ O) {
    extern __shared__ __align__(1024) char dsm[];
    __shared__ int colOff[64];
    const uint32_t sb = smem_u32(dsm);

    const int tid  = threadIdx.x;
    const int wid  = tid >> 5;
    const int lane = tid & 31;
    const int wm = wid >> 1;
    const int wn = wid & 1;

    const int bid = (int)gridDim.x - 1 - (int)blockIdx.x;
    int l = 0;
    while (bid >= c_cum2[l + 1]) ++l;
    const int d     = 2 * l + 1;
    const int off   = c_off12[l];
    const int loc   = bid - c_cum2[l];
    const int tileM = loc / d;
    const int tileN = loc - tileM * d;
    const int Kl    = 64 * d;
    const int nIter = 2 * d;

    const int Abase = 16384 * off;
    const int Bbase = 4096 * off;

    if (tid < 64) {
        const int gc = tileN * 64 + tid;
        const int o  = gc / d;
        const int v  = gc - o * d;
        colOff[tid] = o * IRREP + v * d;
    }

    const int arow = tid & 127;
    const int acsel = (tid >> 7) * 2;
    const int asw = (arow >> 1) & 3;
    const uint32_t adst0 = (uint32_t)(arow * 64 + (((acsel + 0) ^ asw) << 4));
    const uint32_t adst1 = (uint32_t)(arow * 64 + (((acsel + 1) ^ asw) << 4));
    const int asrcRow = Abase + (tileM * 128 + arow) * Kl;

    const int brow = tid >> 2;
    const int bcsel = tid & 3;
    const uint32_t bdst = (uint32_t)(brow * 64 + ((bcsel ^ ((brow >> 1) & 3)) << 4));
    const int bsrcRow = Bbase + (tileN * 64 + brow) * Kl;

    const int a_r0 = wm * 32 + (lane & 15);
    const int a_cbit = lane >> 4;
    const int b_r0 = wn * 32 + (lane & 7) + ((lane >> 4) << 3);
    const int b_cbit = (lane >> 3) & 1;

    uint32_t aoff[2][2], boff[2][2];
#pragma unroll
    for (int mt = 0; mt < 2; mt++) {
        const int row = a_r0 + mt * 16;
        const int sw = (row >> 1) & 3;
#pragma unroll
        for (int ks = 0; ks < 2; ks++)
            aoff[mt][ks] = (uint32_t)(row * 64 + (((ks * 2 + a_cbit) ^ sw) << 4));
    }
#pragma unroll
    for (int ng = 0; ng < 2; ng++) {
        const int row = b_r0 + ng * 16;
        const int sw = (row >> 1) & 3;
#pragma unroll
        for (int ks = 0; ks < 2; ks++)
            boff[ng][ks] = (uint32_t)(row * 64 + (((ks * 2 + b_cbit) ^ sw) << 4));
    }

#pragma unroll
    for (int s = 0; s < 3; s++) {
        if (s < nIter) {
            const uint32_t dst = sb + (uint32_t)(s & 3) * STAGE_BYTES;
            const int kt = s * 32;
            cp16(dst + OFF_SA + adst0, g_Ah + asrcRow + kt + (acsel + 0) * 8);
            cp16(dst + OFF_SA + adst1, g_Ah + asrcRow + kt + (acsel + 1) * 8);
            cp16(dst + OFF_SB + bdst,  g_Bh + bsrcRow + kt + bcsel * 8);
        }
        CP_COMMIT();
    }

    float acc[2][4][4] = {};

    for (int it = 0; it < nIter; ++it) {
        CP_WAIT2();
        __syncthreads();
        {
            const int s = it + 3;
            if (s < nIter) {
                const uint32_t dst = sb + (uint32_t)(s & 3) * STAGE_BYTES;
                const int kt = s * 32;
                cp16(dst + OFF_SA + adst0, g_Ah + asrcRow + kt + (acsel + 0) * 8);
                cp16(dst + OFF_SA + adst1, g_Ah + asrcRow + kt + (acsel + 1) * 8);
                cp16(dst + OFF_SB + bdst,  g_Bh + bsrcRow + kt + bcsel * 8);
            }
            CP_COMMIT();
        }

        const uint32_t sbase = sb + (uint32_t)(it & 3) * STAGE_BYTES;
#pragma unroll
        for (int ks = 0; ks < 2; ks++) {
            uint32_t a[2][4], b[2][4];
#pragma unroll
            for (int mt = 0; mt < 2; mt++)
                LDSM_X4(a[mt][0], a[mt][1], a[mt][2], a[mt][3],
                        sbase + OFF_SA + aoff[mt][ks]);
#pragma unroll
            for (int ng = 0; ng < 2; ng++)
                LDSM_X4(b[ng][0], b[ng][1], b[ng][2], b[ng][3],
                        sbase + OFF_SB + boff[ng][ks]);
#pragma unroll
            for (int mt = 0; mt < 2; mt++)
#pragma unroll
                for (int nt = 0; nt < 4; nt++) {
                    const int ng = nt >> 1, pr = (nt & 1) * 2;
                    mma_f16(acc[mt][nt], a[mt], b[ng][pr], b[ng][pr + 1]);
                }
        }
    }

#pragma unroll
    for (int mt = 0; mt < 2; mt++)
#pragma unroll
        for (int h = 0; h < 2; h++) {
            const int r = tileM * 128 + wm * 32 + mt * 16 + (lane >> 2) + h * 8;
            const int b = r / d;
            const int m = r - b * d;
            float* orow = O + b * RSTRIDE + off + m;
#pragma unroll
            for (int nt = 0; nt < 4; nt++) {
                const int c0 = wn * 32 + nt * 8 + (lane & 3) * 2;
                orow[colOff[c0]]     = acc[mt][nt][h * 2 + 0];
                orow[colOff[c0 + 1]] = acc[mt][nt][h * 2 + 1];
            }
        }
}

// ---------------------------------------------------------------------------
// Launch: two concurrent arms under graph capture.
//   main stream:  wprep -> dprep -> psi_mma ─┐
//   side stream:  xprep ─────────────────────┴─> so3
// ---------------------------------------------------------------------------
extern "C" void kernel_launch(void* const* d_in, const int* in_sizes, int n_in,
                              void* d_out, int out_size) {
    const float* x = (const float*)d_in[0];
    const float* D = (const float*)d_in[1];
    const float* w = (const float*)d_in[2];
    float* out = (float*)d_out;

    static cudaStream_t s2 = nullptr;
    static cudaEvent_t evFork = nullptr, evJoin = nullptr;
    if (s2 == nullptr) {
        cudaStreamCreateWithFlags(&s2, cudaStreamNonBlocking);
        cudaEventCreateWithFlags(&evFork, cudaEventDisableTiming);
        cudaEventCreateWithFlags(&evJoin, cudaEventDisableTiming);
        cudaFuncSetAttribute(psi_mma_kernel, cudaFuncAttributeMaxDynamicSharedMemorySize, SO3_SMEM);
        cudaFuncSetAttribute(so3_kernel,     cudaFuncAttributeMaxDynamicSharedMemorySize, SO3_SMEM);
    }

    // fork: side stream joins the capture via event
    cudaEventRecord(evFork, 0);
    cudaStreamWaitEvent(s2, evFork, 0);

    // side arm: x -> A planes
    xprep_kernel<<<dim3(BATCH, 11, 4), 256, 0, s2>>>(x);
    cudaEventRecord(evJoin, s2);

    // main arm: w,D -> B planes
    wprep_kernel<<<1024, 256>>>(w);
    dprep_kernel<<<dim3(56, 16), dim3(32, 8)>>>(D);
    psi_mma_kernel<<<dim3(28, 32), 256, SO3_SMEM>>>();

    // join, then the big GEMM
    cudaStreamWaitEvent(0, evJoin, 0);
    so3_kernel<<<3542, 256, SO3_SMEM>>>(out);
}